// round 12
// baseline (speedup 1.0000x reference)
#include <cuda_runtime.h>
#include <math.h>

// Problem constants
#define NNODES   50000
#define DISTN    8
#define P_TOT    400000          // NNODES * DISTN
#define KCB      64
#define HIDN     256
#define NGRAPH   64
#define EPSV     0.1f
#define NITER    20
#define STABV    1e-8f
#define CLMAX    1e6f
#define BMARG    (1.0f/64.0f)

#define KBLK     1250            // kmat blocks: 1250 x 320 threads = 10 warps x 32 rows
#define KWARPS   10
#define HBLK     98              // kmat blocks that also build the histogram
#define HCHUNK   512             // nodes per hist block (98*512 >= 50000)

// Prune threshold: exp(-cost/EPS) == 0.0f (fp32, incl. subnormals) requires
// cost/EPS >= ~104. We prune only when the Cauchy-Schwarz lower bound holds:
// ps >= (cmax + sqrt(11))^2  (ps = prefix of ||x||^2)  =>  true cost >= 11
// =>  exp arg >= 110  =>  exactly 0 in the reference too (bit-exact pruning).
#define SQRT11   3.31662479f

// PDL primitives (sm_90+). launch_dependents at kernel ENTRY = let the
// dependent grid's blocks launch/park early (overlap policy). wait = block
// until the upstream grid fully completes and its stores are visible.
#define PDL_TRIGGER() asm volatile("griddepcontrol.launch_dependents;" ::: "memory")
#define PDL_WAIT()    asm volatile("griddepcontrol.wait;" ::: "memory")

// Device scratch (__device__ globals only; zero-initialized at load)
__device__ float          g_Kmat[(size_t)P_TOT * KCB];  // valid only where flag=1
__device__ unsigned char  g_flag[P_TOT];
__device__ float          g_u[P_TOT];
__device__ float          g_ynorm[KCB];
__device__ int            g_cmax_bits;                  // acc by prep, reset by sinkhorn b0
__device__ int            g_nz[NGRAPH];                 // nonzero K rows per graph
__device__ int            g_hist[NGRAPH];               // nodes per graph
__device__ unsigned char  g_oz[64];                     // per-slice "odd words zero"

// ---------------------------------------------------------------------------
// prep: triggers dependents IMMEDIATELY (kmat launches concurrently and parks
// at its wait), then computes ||c_b||^2 -> g_ynorm, atomicMax cmax, detection
// slice, zero g_nz[b]/g_hist[b]. kmat's PDL_WAIT observes all of it.
__global__ void __launch_bounds__(256) prep_kernel(const float* __restrict__ cb,
                                                   const int* __restrict__ b32raw) {
    PDL_TRIGGER();                 // let kmat start ramping NOW

    const int b = blockIdx.x;      // 64 blocks
    const int t = threadIdx.x;     // 256 threads

    __shared__ float red[8];
    __shared__ int   oz[8];

    // ---- ynorm for codebook row b ----
    float v = cb[b * HIDN + t];
    float s = v * v;
    #pragma unroll
    for (int o = 16; o; o >>= 1) s += __shfl_xor_sync(~0u, s, o);
    if ((t & 31) == 0) red[t >> 5] = s;

    // ---- detection slice: odd 32-bit words all zero <=> int64 layout ----
    // (safe range: first NNODES 32-bit words exist under both layouts)
    int allz = 1;
    const int2* p2 = (const int2*)b32raw;
    for (int i = b * 256 + t; i < NNODES / 2; i += 64 * 256)
        if (p2[i].y != 0) allz = 0;
    allz = __all_sync(~0u, allz);
    if ((t & 31) == 0) oz[t >> 5] = allz;
    __syncthreads();

    if (t == 0) {
        float yn = 0.f; int o = 1;
        #pragma unroll
        for (int i = 0; i < 8; i++) { yn += red[i]; o &= oz[i]; }
        g_ynorm[b] = yn;
        g_oz[b] = (unsigned char)o;
        g_nz[b] = 0;
        g_hist[b] = 0;
        atomicMax(&g_cmax_bits, __float_as_int(sqrtf(yn)));
    }
    // grid completion (observed by kmat's PDL_WAIT) publishes all stores
}

// ---------------------------------------------------------------------------
// kmat: triggers sinkhorn's launch immediately. ALL prep-independent work
// (stage-1 loads, full ps reductions, flag zeroing) runs BEFORE the PDL wait;
// after the gate only the threshold compare (+ rare stage-2 / rarer exact
// fallback + histogram for blocks < HBLK) remains.
__global__ void __launch_bounds__(320) kmat_kernel(const float* __restrict__ x,
                                                   const float* __restrict__ cb,
                                                   const void* __restrict__ bidx) {
    PDL_TRIGGER();                 // let sinkhorn pre-launch and park at wait

    __shared__ float xs[KWARPS * HIDN];
    __shared__ int   sh[NGRAPH];

    const int tid  = threadIdx.x;
    const int warp = tid >> 5;         // 0..9
    const int lane = tid & 31;
    const int oct  = lane >> 3;        // 4 rows per load group
    const int ol   = lane & 7;         // 8 lanes per row (8 x 16B = one 128B line)
    const int r0   = (blockIdx.x * KWARPS + warp) * 32;

    // ---- stage 1 loads (prep-independent) ----
    float4 v[8];
    #pragma unroll
    for (int g = 0; g < 8; g++)
        v[g] = __ldcs(&((const float4*)(x + (size_t)(r0 + g * 4 + oct) * HIDN))[ol]);

    // ---- full prefix-norm reductions (prep-independent) ----
    float ps[8];
    #pragma unroll
    for (int g = 0; g < 8; g++) {
        float p = v[g].x*v[g].x + v[g].y*v[g].y + v[g].z*v[g].z + v[g].w*v[g].w;
        p += __shfl_xor_sync(~0u, p, 4);
        p += __shfl_xor_sync(~0u, p, 2);
        p += __shfl_xor_sync(~0u, p, 1);
        ps[g] = p;
    }

    // ---- bulk-zero this warp's 32 flag bytes (prep-independent;
    //      fallback overwrites its rows after the gate) ----
    if (lane < 8) ((unsigned*)(g_flag + r0))[lane] = 0u;

    // ==== gate: wait for prep (hardware PDL, no software spin) ====
    PDL_WAIT();

    const float cmax = __int_as_float(g_cmax_bits);
    const float thr  = (cmax + SQRT11) * (cmax + SQRT11);

    bool pr[8];
    #pragma unroll
    for (int g = 0; g < 8; g++) pr[g] = (ps[g] >= thr);

    bool allp = pr[0] && pr[1] && pr[2] && pr[3] && pr[4] && pr[5] && pr[6] && pr[7];
    unsigned anyb = __ballot_sync(~0u, !allp);

    // ---- stage 2: floats [32,64) only for rows not yet proven ----
    if (anyb) {
        float4 v2[8];
        #pragma unroll
        for (int g = 0; g < 8; g++) {
            v2[g] = make_float4(0.f, 0.f, 0.f, 0.f);
            if (!pr[g])
                v2[g] = __ldcs(&((const float4*)(x + (size_t)(r0 + g * 4 + oct) * HIDN))[8 + ol]);
        }
        #pragma unroll
        for (int g = 0; g < 8; g++) {
            float p = v2[g].x*v2[g].x + v2[g].y*v2[g].y + v2[g].z*v2[g].z + v2[g].w*v2[g].w;
            p += __shfl_xor_sync(~0u, p, 4);
            p += __shfl_xor_sync(~0u, p, 2);
            p += __shfl_xor_sync(~0u, p, 1);
            ps[g] += p;
            pr[g] = pr[g] || (ps[g] >= thr);
        }
        allp = pr[0] && pr[1] && pr[2] && pr[3] && pr[4] && pr[5] && pr[6] && pr[7];
        anyb = __ballot_sync(~0u, !allp);
    }
    __syncwarp();

    // ---- rare exact fallback (cold path; general correctness) ----
    if (anyb) {
        bool ozl = (g_oz[lane] != 0) && (g_oz[lane + 32] != 0);
        const int is64 = __all_sync(~0u, ozl);

        unsigned needf = 0;
        #pragma unroll
        for (int g = 0; g < 8; g++) {
            unsigned bg = __ballot_sync(~0u, !pr[g]);
            needf |= ((bg        & 1u) << (g * 4 + 0))
                   | (((bg >> 8)  & 1u) << (g * 4 + 1))
                   | (((bg >> 16) & 1u) << (g * 4 + 2))
                   | (((bg >> 24) & 1u) << (g * 4 + 3));
        }

        float4* sm = (float4*)(xs + warp * HIDN);
        while (needf) {
            const int idx = __ffs(needf) - 1;
            needf &= needf - 1;
            const int r = r0 + idx;

            const float4* xr4 = (const float4*)(x + (size_t)r * HIDN);
            float4 va = xr4[lane];
            float4 vb = xr4[32 + lane];
            float s = va.x*va.x + va.y*va.y + va.z*va.z + va.w*va.w
                    + vb.x*vb.x + vb.y*vb.y + vb.z*vb.z + vb.w*vb.w;
            #pragma unroll
            for (int o = 16; o; o >>= 1) s += __shfl_xor_sync(~0u, s, o);
            const float xn = s;

            sm[lane] = va;
            sm[32 + lane] = vb;
            __syncwarp();

            const int c0 = lane, c1 = lane + 32;
            const float4* cb0 = (const float4*)(cb + (size_t)c0 * HIDN);
            const float4* cb1 = (const float4*)(cb + (size_t)c1 * HIDN);
            float d0 = 0.f, d1 = 0.f;
            #pragma unroll 8
            for (int t = 0; t < HIDN / 4; t++) {
                float4 xv = sm[t];
                float4 p = cb0[t], q = cb1[t];
                d0 += xv.x*p.x + xv.y*p.y + xv.z*p.z + xv.w*p.w;
                d1 += xv.x*q.x + xv.y*q.y + xv.z*q.z + xv.w*q.w;
            }
            float cost0 = xn + g_ynorm[c0] - 2.f * d0;
            float cost1 = xn + g_ynorm[c1] - 2.f * d1;

            // reference semantics: nan/inf cost -> Kmat = STAB (exp(-inf)=0 stays 0)
            float k0, k1;
            unsigned bits0 = __float_as_uint(cost0) & 0x7fffffffu;
            unsigned bits1 = __float_as_uint(cost1) & 0x7fffffffu;
            if (bits0 > 0x7f800000u) k0 = STABV;
            else                     k0 = expf(-fmaxf(cost0, 0.f) / EPSV);
            if (bits1 > 0x7f800000u) k1 = STABV;
            else                     k1 = expf(-fmaxf(cost1, 0.f) / EPSV);

            g_Kmat[(size_t)r * KCB + c0] = k0;
            g_Kmat[(size_t)r * KCB + c1] = k1;

            unsigned nz = __ballot_sync(~0u, (k0 != 0.f) || (k1 != 0.f));
            if (lane == 0) {
                g_flag[r] = nz ? 1 : 0;
                if (nz) {
                    const int node = r >> 3;
                    int g = is64 ? (int)((const long long*)bidx)[node]
                                 : ((const int*)bidx)[node];
                    g = min(max(g, 0), NGRAPH - 1);
                    atomicAdd(&g_nz[g], 1);
                }
            }
            __syncwarp();
        }
    }

    // ---- per-graph node histogram (blocks < HBLK; g_hist zeroed by prep) ----
    if (blockIdx.x < HBLK) {
        bool ozl = (g_oz[lane] != 0) && (g_oz[lane + 32] != 0);
        const int is64h = __all_sync(~0u, ozl);
        if (tid < NGRAPH) sh[tid] = 0;
        __syncthreads();
        const long long* b64 = (const long long*)bidx;
        const int*       b32 = (const int*)bidx;
        const int n0 = blockIdx.x * HCHUNK;
        const int n1 = min(n0 + HCHUNK, NNODES);
        for (int i = n0 + tid; i < n1; i += 320) {
            int g = is64h ? (int)b64[i] : b32[i];
            g = min(max(g, 0), NGRAPH - 1);
            atomicAdd(&sh[g], 1);
        }
        __syncthreads();
        if (tid < NGRAPH && sh[tid]) atomicAdd(&g_hist[tid], sh[tid]);
    }
    // grid completion (observed by sinkhorn's PDL_WAIT) publishes all stores
}

// ---------------------------------------------------------------------------
// sinkhorn: one block per graph; g_hist precomputed by kmat. Fast path when
// the graph's K rows are all exactly zero (guaranteed exact by pruning).
// Block 0 resets g_cmax_bits for the next replay's prep.
__global__ void __launch_bounds__(256) sinkhorn_kernel(float* __restrict__ out) {
    __shared__ float sV[64], sKTU[64], sW[64];
    __shared__ int   sRange[2];
    __shared__ float sTot;

    PDL_WAIT();   // park until kmat completes (stores visible)

    const int b    = blockIdx.x;
    const int tid  = threadIdx.x;
    const int lane = tid & 31;
    const int warp = tid >> 5;        // 8 warps

    if (tid == 0) {
        int s = 0;
        for (int g = 0; g < b; g++) s += g_hist[g];
        sRange[0] = s * DISTN;
        sRange[1] = (s + g_hist[b]) * DISTN;
    }
    if (tid < 64) { sV[tid] = 1.f; sKTU[tid] = 0.f; sW[tid] = 0.f; }
    __syncthreads();

    const int rs = sRange[0], re = sRange[1];

    // Fast path: every K row of this graph is exactly zero.
    if (g_nz[b] == 0) {
        if (tid < 64) out[b * KCB + tid] = (re == rs) ? 0.f : BMARG;
        if (b == 0 && tid == 0) g_cmax_bits = 0;
        return;
    }

    // -------- general Sinkhorn path (correct; never taken on this data) ----
    const float aa = 1.f / fmaxf((float)(re - rs), 1.f);

    for (int iter = 0; iter < NITER; iter++) {
        float v0 = sV[lane], v1 = sV[lane + 32];
        float ktu0 = 0.f, ktu1 = 0.f;
        for (int r = rs + warp; r < re; r += 8) {
            if (!g_flag[r]) continue;
            float k0 = g_Kmat[(size_t)r * KCB + lane];
            float k1 = g_Kmat[(size_t)r * KCB + 32 + lane];
            float kv = k0 * v0 + k1 * v1;
            #pragma unroll
            for (int o = 16; o; o >>= 1) kv += __shfl_xor_sync(~0u, kv, o);
            float u = aa / fmaxf(kv, STABV);
            if (iter == NITER - 1 && lane == 0) g_u[r] = u;
            ktu0 += k0 * u;
            ktu1 += k1 * u;
        }
        atomicAdd(&sKTU[lane], ktu0);
        atomicAdd(&sKTU[lane + 32], ktu1);
        __syncthreads();
        if (tid < 64) {
            sV[tid] = BMARG / fmaxf(sKTU[tid], STABV);
            sKTU[tid] = 0.f;
        }
        __syncthreads();
    }

    {
        float w0 = 0.f, w1 = 0.f;
        for (int r = rs + warp; r < re; r += 8) {
            if (!g_flag[r]) continue;
            float uc = fminf(fmaxf(g_u[r], STABV), CLMAX);
            float k0 = g_Kmat[(size_t)r * KCB + lane];
            float k1 = g_Kmat[(size_t)r * KCB + 32 + lane];
            w0 += k0 * uc;
            w1 += k1 * uc;
        }
        atomicAdd(&sW[lane], w0);
        atomicAdd(&sW[lane + 32], w1);
    }
    __syncthreads();
    if (tid < 64) {
        float vc = fminf(fmaxf(sV[tid], STABV), CLMAX);
        sW[tid] = sW[tid] * vc;
    }
    __syncthreads();
    if (tid < 32) {
        float t = sW[tid] + sW[tid + 32];
        #pragma unroll
        for (int o = 16; o; o >>= 1) t += __shfl_xor_sync(~0u, t, o);
        if (tid == 0) sTot = t;
    }
    __syncthreads();
    if (tid < 64) {
        float total = sTot;
        float val = (total > STABV) ? (sW[tid] / fmaxf(total, STABV)) : BMARG;
        out[b * KCB + tid] = ((re - rs) == 0) ? 0.f : val;
    }
    if (b == 0 && tid == 0) g_cmax_bits = 0;
}

// ---------------------------------------------------------------------------
extern "C" void kernel_launch(void* const* d_in, const int* in_sizes, int n_in,
                              void* d_out, int out_size) {
    const float* x    = (const float*)d_in[0];   // node_distributions [50000,8,256]
    const void*  bidx = d_in[1];                 // batch_idx [50000] int64 or int32
    const float* cb   = (const float*)d_in[2];   // codebook [64,256]
    float* out = (float*)d_out;                  // [64,64] float32

    prep_kernel<<<64, 256>>>(cb, (const int*)bidx);

    cudaLaunchAttribute attr[1];
    attr[0].id = cudaLaunchAttributeProgrammaticStreamSerialization;
    attr[0].val.programmaticStreamSerializationAllowed = 1;

    {
        cudaLaunchConfig_t cfg = {};
        cfg.gridDim  = dim3(KBLK);
        cfg.blockDim = dim3(320);
        cfg.stream   = 0;
        cfg.attrs    = attr;
        cfg.numAttrs = 1;
        cudaLaunchKernelEx(&cfg, kmat_kernel, x, cb, bidx);
    }
    {
        cudaLaunchConfig_t cfg = {};
        cfg.gridDim  = dim3(NGRAPH);
        cfg.blockDim = dim3(256);
        cfg.stream   = 0;
        cfg.attrs    = attr;
        cfg.numAttrs = 1;
        cudaLaunchKernelEx(&cfg, sinkhorn_kernel, out);
    }
}

// round 13
// speedup vs baseline: 1.1235x; 1.1235x over previous
#include <cuda_runtime.h>
#include <math.h>

// Problem constants
#define NNODES   50000
#define DISTN    8
#define P_TOT    400000          // NNODES * DISTN
#define KCB      64
#define HIDN     256
#define NGRAPH   64
#define EPSV     0.1f
#define NITER    20
#define STABV    1e-8f
#define CLMAX    1e6f
#define BMARG    (1.0f/64.0f)

#define KBLK     1250            // kmat blocks: 1250 x 320 threads = 10 warps x 32 rows
#define KWARPS   10
#define HBLK     98              // kmat blocks that also build the histogram
#define HCHUNK   512             // nodes per hist block (98*512 >= 50000)

// Prune threshold: expf(-t) rounds to 0.0f (fp32, incl. subnormals) for
// t >= ~104.4, i.e. cost >= 10.44. We prune when the Cauchy-Schwarz lower
// bound holds: ps >= (cmax + sqrt(10.5))^2 (ps = prefix of ||x||^2)
// => true cost >= 10.5 => exp arg >= 105 => exactly 0 in the reference too.
#define SQRTPC   3.24037035f     // sqrt(10.5)

// PDL primitives (sm_90+). launch_dependents at kernel ENTRY = let the
// dependent grid's blocks launch/park early (overlap policy). wait = block
// until the upstream grid fully completes and its stores are visible.
#define PDL_TRIGGER() asm volatile("griddepcontrol.launch_dependents;" ::: "memory")
#define PDL_WAIT()    asm volatile("griddepcontrol.wait;" ::: "memory")

// Device scratch (__device__ globals only; zero-initialized at load)
__device__ float          g_Kmat[(size_t)P_TOT * KCB];  // valid only where flag=1
__device__ unsigned char  g_flag[P_TOT];
__device__ float          g_u[P_TOT];
__device__ float          g_ynorm[KCB];
__device__ int            g_cmax_bits;                  // acc by prep, reset by sinkhorn b0
__device__ int            g_nz[NGRAPH];                 // nonzero K rows per graph
__device__ int            g_hist[NGRAPH];               // nodes per graph
__device__ unsigned char  g_oz[64];                     // per-slice "odd words zero"

// ---------------------------------------------------------------------------
// prep: triggers dependents IMMEDIATELY (kmat launches concurrently and parks
// at its wait), then computes ||c_b||^2 -> g_ynorm, atomicMax cmax, detection
// slice, zero g_nz[b]/g_hist[b]. kmat's PDL_WAIT observes all of it.
__global__ void __launch_bounds__(256) prep_kernel(const float* __restrict__ cb,
                                                   const int* __restrict__ b32raw) {
    PDL_TRIGGER();                 // let kmat start ramping NOW

    const int b = blockIdx.x;      // 64 blocks
    const int t = threadIdx.x;     // 256 threads

    __shared__ float red[8];
    __shared__ int   oz[8];

    // ---- ynorm for codebook row b ----
    float v = cb[b * HIDN + t];
    float s = v * v;
    #pragma unroll
    for (int o = 16; o; o >>= 1) s += __shfl_xor_sync(~0u, s, o);
    if ((t & 31) == 0) red[t >> 5] = s;

    // ---- detection slice: odd 32-bit words all zero <=> int64 layout ----
    // (safe range: first NNODES 32-bit words exist under both layouts)
    int allz = 1;
    const int2* p2 = (const int2*)b32raw;
    for (int i = b * 256 + t; i < NNODES / 2; i += 64 * 256)
        if (p2[i].y != 0) allz = 0;
    allz = __all_sync(~0u, allz);
    if ((t & 31) == 0) oz[t >> 5] = allz;
    __syncthreads();

    if (t == 0) {
        float yn = 0.f; int o = 1;
        #pragma unroll
        for (int i = 0; i < 8; i++) { yn += red[i]; o &= oz[i]; }
        g_ynorm[b] = yn;
        g_oz[b] = (unsigned char)o;
        g_nz[b] = 0;
        g_hist[b] = 0;
        atomicMax(&g_cmax_bits, __float_as_int(sqrtf(yn)));
    }
    // grid completion (observed by kmat's PDL_WAIT) publishes all stores
}

// ---------------------------------------------------------------------------
// kmat: triggers sinkhorn's launch immediately, issues stage-1 loads (which
// do not depend on prep), THEN waits for prep. One warp = 32 rows, 8
// unpredicated coalesced LDG.128 (MLP=8), single-compare prune, rare stage 2,
// rarer exact fallback. Blocks < HBLK also build the node histogram.
__global__ void __launch_bounds__(320) kmat_kernel(const float* __restrict__ x,
                                                   const float* __restrict__ cb,
                                                   const void* __restrict__ bidx) {
    PDL_TRIGGER();                 // let sinkhorn pre-launch and park at wait

    __shared__ float xs[KWARPS * HIDN];
    __shared__ int   sh[NGRAPH];

    const int tid  = threadIdx.x;
    const int warp = tid >> 5;         // 0..9
    const int lane = tid & 31;
    const int oct  = lane >> 3;        // 4 rows per load group
    const int ol   = lane & 7;         // 8 lanes per row (8 x 16B = one 128B line)
    const int r0   = (blockIdx.x * KWARPS + warp) * 32;

    // ---- stage 1 loads first (x is independent of prep) ----
    float4 v[8];
    #pragma unroll
    for (int g = 0; g < 8; g++)
        v[g] = __ldcs(&((const float4*)(x + (size_t)(r0 + g * 4 + oct) * HIDN))[ol]);

    // ---- now synchronize with prep (hardware PDL, no software spin) ----
    PDL_WAIT();

    const float cmax = __int_as_float(g_cmax_bits);
    const float thr  = (cmax + SQRTPC) * (cmax + SQRTPC);

    float ps[8];
    bool  pr[8];
    #pragma unroll
    for (int g = 0; g < 8; g++) {
        float p = v[g].x*v[g].x + v[g].y*v[g].y + v[g].z*v[g].z + v[g].w*v[g].w;
        p += __shfl_xor_sync(~0u, p, 4);
        p += __shfl_xor_sync(~0u, p, 2);
        p += __shfl_xor_sync(~0u, p, 1);
        ps[g] = p;
        pr[g] = (p >= thr);
    }

    bool allp = pr[0] && pr[1] && pr[2] && pr[3] && pr[4] && pr[5] && pr[6] && pr[7];
    unsigned anyb = __ballot_sync(~0u, !allp);

    // ---- stage 2: floats [32,64) only for rows not yet proven ----
    if (anyb) {
        float4 v2[8];
        #pragma unroll
        for (int g = 0; g < 8; g++) {
            v2[g] = make_float4(0.f, 0.f, 0.f, 0.f);
            if (!pr[g])
                v2[g] = __ldcs(&((const float4*)(x + (size_t)(r0 + g * 4 + oct) * HIDN))[8 + ol]);
        }
        #pragma unroll
        for (int g = 0; g < 8; g++) {
            float p = v2[g].x*v2[g].x + v2[g].y*v2[g].y + v2[g].z*v2[g].z + v2[g].w*v2[g].w;
            p += __shfl_xor_sync(~0u, p, 4);
            p += __shfl_xor_sync(~0u, p, 2);
            p += __shfl_xor_sync(~0u, p, 1);
            ps[g] += p;
            pr[g] = pr[g] || (ps[g] >= thr);
        }
        allp = pr[0] && pr[1] && pr[2] && pr[3] && pr[4] && pr[5] && pr[6] && pr[7];
        anyb = __ballot_sync(~0u, !allp);
    }

    // ---- bulk-zero this warp's 32 flag bytes (fallback overwrites its rows) ----
    if (lane < 8) ((unsigned*)(g_flag + r0))[lane] = 0u;
    __syncwarp();

    // ---- rare exact fallback (cold path; general correctness) ----
    if (anyb) {
        bool ozl = (g_oz[lane] != 0) && (g_oz[lane + 32] != 0);
        const int is64 = __all_sync(~0u, ozl);

        unsigned needf = 0;
        #pragma unroll
        for (int g = 0; g < 8; g++) {
            unsigned bg = __ballot_sync(~0u, !pr[g]);
            needf |= ((bg        & 1u) << (g * 4 + 0))
                   | (((bg >> 8)  & 1u) << (g * 4 + 1))
                   | (((bg >> 16) & 1u) << (g * 4 + 2))
                   | (((bg >> 24) & 1u) << (g * 4 + 3));
        }

        float4* sm = (float4*)(xs + warp * HIDN);
        while (needf) {
            const int idx = __ffs(needf) - 1;
            needf &= needf - 1;
            const int r = r0 + idx;

            const float4* xr4 = (const float4*)(x + (size_t)r * HIDN);
            float4 va = xr4[lane];
            float4 vb = xr4[32 + lane];
            float s = va.x*va.x + va.y*va.y + va.z*va.z + va.w*va.w
                    + vb.x*vb.x + vb.y*vb.y + vb.z*vb.z + vb.w*vb.w;
            #pragma unroll
            for (int o = 16; o; o >>= 1) s += __shfl_xor_sync(~0u, s, o);
            const float xn = s;

            sm[lane] = va;
            sm[32 + lane] = vb;
            __syncwarp();

            const int c0 = lane, c1 = lane + 32;
            const float4* cb0 = (const float4*)(cb + (size_t)c0 * HIDN);
            const float4* cb1 = (const float4*)(cb + (size_t)c1 * HIDN);
            float d0 = 0.f, d1 = 0.f;
            #pragma unroll 8
            for (int t = 0; t < HIDN / 4; t++) {
                float4 xv = sm[t];
                float4 p = cb0[t], q = cb1[t];
                d0 += xv.x*p.x + xv.y*p.y + xv.z*p.z + xv.w*p.w;
                d1 += xv.x*q.x + xv.y*q.y + xv.z*q.z + xv.w*q.w;
            }
            float cost0 = xn + g_ynorm[c0] - 2.f * d0;
            float cost1 = xn + g_ynorm[c1] - 2.f * d1;

            // reference semantics: nan/inf cost -> Kmat = STAB (exp(-inf)=0 stays 0)
            float k0, k1;
            unsigned bits0 = __float_as_uint(cost0) & 0x7fffffffu;
            unsigned bits1 = __float_as_uint(cost1) & 0x7fffffffu;
            if (bits0 > 0x7f800000u) k0 = STABV;
            else                     k0 = expf(-fmaxf(cost0, 0.f) / EPSV);
            if (bits1 > 0x7f800000u) k1 = STABV;
            else                     k1 = expf(-fmaxf(cost1, 0.f) / EPSV);

            g_Kmat[(size_t)r * KCB + c0] = k0;
            g_Kmat[(size_t)r * KCB + c1] = k1;

            unsigned nz = __ballot_sync(~0u, (k0 != 0.f) || (k1 != 0.f));
            if (lane == 0) {
                g_flag[r] = nz ? 1 : 0;
                if (nz) {
                    const int node = r >> 3;
                    int g = is64 ? (int)((const long long*)bidx)[node]
                                 : ((const int*)bidx)[node];
                    g = min(max(g, 0), NGRAPH - 1);
                    atomicAdd(&g_nz[g], 1);
                }
            }
            __syncwarp();
        }
    }

    // ---- per-graph node histogram (blocks < HBLK; g_hist zeroed by prep) ----
    if (blockIdx.x < HBLK) {
        bool ozl = (g_oz[lane] != 0) && (g_oz[lane + 32] != 0);
        const int is64h = __all_sync(~0u, ozl);
        if (tid < NGRAPH) sh[tid] = 0;
        __syncthreads();
        const long long* b64 = (const long long*)bidx;
        const int*       b32 = (const int*)bidx;
        const int n0 = blockIdx.x * HCHUNK;
        const int n1 = min(n0 + HCHUNK, NNODES);
        for (int i = n0 + tid; i < n1; i += 320) {
            int g = is64h ? (int)b64[i] : b32[i];
            g = min(max(g, 0), NGRAPH - 1);
            atomicAdd(&sh[g], 1);
        }
        __syncthreads();
        if (tid < NGRAPH && sh[tid]) atomicAdd(&g_hist[tid], sh[tid]);
    }
    // grid completion (observed by sinkhorn's PDL_WAIT) publishes all stores
}

// ---------------------------------------------------------------------------
// sinkhorn: one block per graph. FAST PATH FIRST: when g_nz[b]==0 (all K rows
// of graph b exactly zero — guaranteed exact by pruning), the output needs
// only g_hist[b] (empty-graph test), no prefix scan. The general path (never
// taken on this data) computes the prefix range and runs full Sinkhorn.
// Block 0 resets g_cmax_bits for the next replay's prep.
__global__ void __launch_bounds__(256) sinkhorn_kernel(float* __restrict__ out) {
    __shared__ float sV[64], sKTU[64], sW[64];
    __shared__ int   sRange[2];
    __shared__ float sTot;

    PDL_WAIT();   // park until kmat completes (stores visible)

    const int b    = blockIdx.x;
    const int tid  = threadIdx.x;
    const int lane = tid & 31;
    const int warp = tid >> 5;        // 8 warps

    // Fast path: no prefix scan needed — just own bin count.
    if (g_nz[b] == 0) {
        const int cnt = g_hist[b];
        if (tid < 64) out[b * KCB + tid] = (cnt == 0) ? 0.f : BMARG;
        if (b == 0 && tid == 0) g_cmax_bits = 0;
        return;
    }

    // -------- general Sinkhorn path (correct; never taken on this data) ----
    if (tid == 0) {
        int s = 0;
        for (int g = 0; g < b; g++) s += g_hist[g];
        sRange[0] = s * DISTN;
        sRange[1] = (s + g_hist[b]) * DISTN;
    }
    if (tid < 64) { sV[tid] = 1.f; sKTU[tid] = 0.f; sW[tid] = 0.f; }
    __syncthreads();

    const int rs = sRange[0], re = sRange[1];
    const float aa = 1.f / fmaxf((float)(re - rs), 1.f);

    for (int iter = 0; iter < NITER; iter++) {
        float v0 = sV[lane], v1 = sV[lane + 32];
        float ktu0 = 0.f, ktu1 = 0.f;
        for (int r = rs + warp; r < re; r += 8) {
            if (!g_flag[r]) continue;
            float k0 = g_Kmat[(size_t)r * KCB + lane];
            float k1 = g_Kmat[(size_t)r * KCB + 32 + lane];
            float kv = k0 * v0 + k1 * v1;
            #pragma unroll
            for (int o = 16; o; o >>= 1) kv += __shfl_xor_sync(~0u, kv, o);
            float u = aa / fmaxf(kv, STABV);
            if (iter == NITER - 1 && lane == 0) g_u[r] = u;
            ktu0 += k0 * u;
            ktu1 += k1 * u;
        }
        atomicAdd(&sKTU[lane], ktu0);
        atomicAdd(&sKTU[lane + 32], ktu1);
        __syncthreads();
        if (tid < 64) {
            sV[tid] = BMARG / fmaxf(sKTU[tid], STABV);
            sKTU[tid] = 0.f;
        }
        __syncthreads();
    }

    {
        float w0 = 0.f, w1 = 0.f;
        for (int r = rs + warp; r < re; r += 8) {
            if (!g_flag[r]) continue;
            float uc = fminf(fmaxf(g_u[r], STABV), CLMAX);
            float k0 = g_Kmat[(size_t)r * KCB + lane];
            float k1 = g_Kmat[(size_t)r * KCB + 32 + lane];
            w0 += k0 * uc;
            w1 += k1 * uc;
        }
        atomicAdd(&sW[lane], w0);
        atomicAdd(&sW[lane + 32], w1);
    }
    __syncthreads();
    if (tid < 64) {
        float vc = fminf(fmaxf(sV[tid], STABV), CLMAX);
        sW[tid] = sW[tid] * vc;
    }
    __syncthreads();
    if (tid < 32) {
        float t = sW[tid] + sW[tid + 32];
        #pragma unroll
        for (int o = 16; o; o >>= 1) t += __shfl_xor_sync(~0u, t, o);
        if (tid == 0) sTot = t;
    }
    __syncthreads();
    if (tid < 64) {
        float total = sTot;
        float val = (total > STABV) ? (sW[tid] / fmaxf(total, STABV)) : BMARG;
        out[b * KCB + tid] = ((re - rs) == 0) ? 0.f : val;
    }
    if (b == 0 && tid == 0) g_cmax_bits = 0;
}

// ---------------------------------------------------------------------------
extern "C" void kernel_launch(void* const* d_in, const int* in_sizes, int n_in,
                              void* d_out, int out_size) {
    const float* x    = (const float*)d_in[0];   // node_distributions [50000,8,256]
    const void*  bidx = d_in[1];                 // batch_idx [50000] int64 or int32
    const float* cb   = (const float*)d_in[2];   // codebook [64,256]
    float* out = (float*)d_out;                  // [64,64] float32

    prep_kernel<<<64, 256>>>(cb, (const int*)bidx);

    cudaLaunchAttribute attr[1];
    attr[0].id = cudaLaunchAttributeProgrammaticStreamSerialization;
    attr[0].val.programmaticStreamSerializationAllowed = 1;

    {
        cudaLaunchConfig_t cfg = {};
        cfg.gridDim  = dim3(KBLK);
        cfg.blockDim = dim3(320);
        cfg.stream   = 0;
        cfg.attrs    = attr;
        cfg.numAttrs = 1;
        cudaLaunchKernelEx(&cfg, kmat_kernel, x, cb, bidx);
    }
    {
        cudaLaunchConfig_t cfg = {};
        cfg.gridDim  = dim3(NGRAPH);
        cfg.blockDim = dim3(256);
        cfg.stream   = 0;
        cfg.attrs    = attr;
        cfg.numAttrs = 1;
        cudaLaunchKernelEx(&cfg, sinkhorn_kernel, out);
    }
}